// round 1
// baseline (speedup 1.0000x reference)
#include <cuda_runtime.h>
#include <cuda_bf16.h>

// STDP collapses because TE=1: e_t = e_{t-1} - e_{t-1}/1 + (x_t q_t^T - p_t y_t^T)
//                                  = x_t q_t^T - p_t y_t^T     (decay term is exactly 0)
// => final e = x_T ⊗ q_T - p_T ⊗ y_T, with x,y the 1-D filtered traces.
//
// Shapes (fixed by the problem): T=256, N_PRE=N_POST=1024.
// Hyperparams: AP=AN=1, TP=TN=2 (=> x += (p - x)*0.5), TE=1.

#define N_MAX 1024

__device__ float g_x[N_MAX];   // final pre-trace  x_T
__device__ float g_y[N_MAX];   // final post-trace y_T

// Kernel 1: 2048 threads, each runs one column's 256-step recurrence.
// Threads [0, N) handle pre -> g_x; threads [N, 2N) handle post -> g_y.
// Loads are coalesced across the warp (consecutive columns, row-major input).
__global__ void stdp_trace_kernel(const float* __restrict__ pre,
                                  const float* __restrict__ post,
                                  int T, int N)
{
    int i = blockIdx.x * blockDim.x + threadIdx.x;
    if (i >= 2 * N) return;
    const float* src = (i < N) ? pre : post;
    int col = (i < N) ? i : i - N;

    float acc = 0.0f;
    // Replicate the reference's fp32 update order exactly:
    //   x = x + (-x + AP*p)/TP  ==  x += (p - x) * 0.5f
    #pragma unroll 8
    for (int t = 0; t < T; ++t) {
        float s = src[(size_t)t * N + col];
        acc = acc + (s - acc) * 0.5f;
    }
    if (i < N) g_x[col] = acc;
    else       g_y[col] = acc;
}

// Kernel 2: out[i][j] = x[i]*q[j] - p[i]*y[j] with p,q = last input rows.
// One block per output row; 256 threads x float4 covers 1024 columns.
// Pure store-bandwidth bound: 4 MB of perfectly coalesced 16B stores.
__global__ void stdp_outer_kernel(const float* __restrict__ pre,
                                  const float* __restrict__ post,
                                  float* __restrict__ out,
                                  int T, int N)
{
    int i  = blockIdx.x;      // output row (pre index)
    int j4 = threadIdx.x;     // float4 column group

    float xi = g_x[i];
    float pi = pre[(size_t)(T - 1) * N + i];   // uniform across block

    const float4* q4 = reinterpret_cast<const float4*>(post + (size_t)(T - 1) * N);
    const float4* y4 = reinterpret_cast<const float4*>(g_y);
    float4 q = q4[j4];
    float4 y = y4[j4];

    float4 r;
    r.x = xi * q.x - pi * y.x;
    r.y = xi * q.y - pi * y.y;
    r.z = xi * q.z - pi * y.z;
    r.w = xi * q.w - pi * y.w;

    reinterpret_cast<float4*>(out)[(size_t)i * (N / 4) + j4] = r;
}

extern "C" void kernel_launch(void* const* d_in, const int* in_sizes, int n_in,
                              void* d_out, int out_size)
{
    const float* pre  = (const float*)d_in[0];   // [T, N_pre]
    const float* post = (const float*)d_in[1];   // [T, N_post]
    float* out = (float*)d_out;                  // [N_pre, N_post]

    // N_pre = N_post = sqrt(out_size) for this problem (1024); T from input size.
    int N = 1;
    while ((long long)N * N < (long long)out_size) N <<= 1;   // out_size = 1024*1024 -> N=1024
    int T = in_sizes[0] / N;                                   // 256

    // Kernel 1: 2N threads total.
    int threads = 256;
    int blocks  = (2 * N + threads - 1) / threads;
    stdp_trace_kernel<<<blocks, threads>>>(pre, post, T, N);

    // Kernel 2: one block per row, N/4 threads (float4 per thread).
    stdp_outer_kernel<<<N, N / 4>>>(pre, post, out, T, N);
}

// round 2
// speedup vs baseline: 1.6942x; 1.6942x over previous
#include <cuda_runtime.h>
#include <cuda_bf16.h>

// STDP collapses because TE=1: e_t = e_{t-1} - e_{t-1}/1 + (x_t q_t^T - p_t y_t^T)
//                                  = x_t q_t^T - p_t y_t^T    (decay term exactly 0)
// => final e = x_T ⊗ q_T - p_T ⊗ y_T, with x,y the per-column filtered traces
//    x <- x + (p - x)*0.5 run over T steps.
//
// Trace parallelization: the 0.5-decay recurrence over a 32-step chunk is the
// affine map  out = A*in + b  with A = 2^-32 (exact in fp32). Composing 4
// chunks covers the last 128 steps; anything older is scaled by 2^-128 ~ 0,
// so we truncate there (abs error < 6e-39).
//
// Shapes fixed by the problem: T=256, N_PRE=N_POST=1024.

#define N_MAX 1024
#define NCHUNK 4
#define CHUNK 32
#define COLS_PER_BLOCK 64          // NCHUNK * COLS_PER_BLOCK = 256 threads
#define ROWS_PER_BLOCK 8           // outer kernel rows per block

__device__ float g_x[N_MAX];   // final pre-trace  x_T
__device__ float g_y[N_MAX];   // final post-trace y_T

// Kernel 1: chunked trace. 2N columns x NCHUNK chunks of 32 timesteps.
// Warp lanes cover consecutive columns -> fully coalesced 128B loads.
__global__ void stdp_trace_kernel(const float* __restrict__ pre,
                                  const float* __restrict__ post,
                                  int T, int N)
{
    int colLocal = threadIdx.x & (COLS_PER_BLOCK - 1);
    int chunk    = threadIdx.x >> 6;               // 0..3
    int gcol     = blockIdx.x * COLS_PER_BLOCK + colLocal;   // 0..2N-1
    if (gcol >= 2 * N) return;

    const float* src = (gcol < N) ? pre : post;
    int col = (gcol < N) ? gcol : gcol - N;

    int t0 = T - NCHUNK * CHUNK + chunk * CHUNK;   // last 128 steps only

    // Run the recurrence from 0 over this chunk (b term of the affine map).
    float acc = 0.0f;
    #pragma unroll
    for (int k = 0; k < CHUNK; ++k) {
        float s = __ldg(&src[(size_t)(t0 + k) * N + col]);
        acc = acc + (s - acc) * 0.5f;
    }

    __shared__ float sb[NCHUNK][COLS_PER_BLOCK];
    sb[chunk][colLocal] = acc;
    __syncthreads();

    if (chunk == 0) {
        const float A = 2.3283064365386963e-10f;   // 2^-32, exact
        float x = sb[0][colLocal];                 // earliest chunk
        #pragma unroll
        for (int c = 1; c < NCHUNK; ++c)
            x = x * A + sb[c][colLocal];
        if (gcol < N) g_x[col] = x;
        else          g_y[col] = x;
    }
}

// Kernel 2: out[i][j] = x[i]*q[j] - p[i]*y[j], p/q = last input rows.
// 128 blocks x 256 threads; each thread loads q4/y4 once and stores 8 rows.
__global__ void stdp_outer_kernel(const float* __restrict__ pre,
                                  const float* __restrict__ post,
                                  float* __restrict__ out,
                                  int T, int N)
{
    int j4   = threadIdx.x;                 // float4 column group, N/4 per row
    int row0 = blockIdx.x * ROWS_PER_BLOCK;
    int N4   = N >> 2;

    const float* preLast  = pre  + (size_t)(T - 1) * N;
    const float* postLast = post + (size_t)(T - 1) * N;

    // Uniform-per-block scalars; prefetch all 16 loads up front for MLP.
    float xi[ROWS_PER_BLOCK], pi[ROWS_PER_BLOCK];
    #pragma unroll
    for (int r = 0; r < ROWS_PER_BLOCK; ++r) {
        xi[r] = g_x[row0 + r];
        pi[r] = __ldg(&preLast[row0 + r]);
    }

    float4 q = reinterpret_cast<const float4*>(postLast)[j4];
    float4 y = reinterpret_cast<const float4*>(g_y)[j4];

    float4* o = reinterpret_cast<float4*>(out);
    #pragma unroll
    for (int r = 0; r < ROWS_PER_BLOCK; ++r) {
        float4 v;
        v.x = xi[r] * q.x - pi[r] * y.x;
        v.y = xi[r] * q.y - pi[r] * y.y;
        v.z = xi[r] * q.z - pi[r] * y.z;
        v.w = xi[r] * q.w - pi[r] * y.w;
        o[(size_t)(row0 + r) * N4 + j4] = v;
    }
}

extern "C" void kernel_launch(void* const* d_in, const int* in_sizes, int n_in,
                              void* d_out, int out_size)
{
    const float* pre  = (const float*)d_in[0];   // [T, N_pre]
    const float* post = (const float*)d_in[1];   // [T, N_post]
    float* out = (float*)d_out;                  // [N_pre, N_post]

    // N_pre = N_post = sqrt(out_size) (1024 here); T from input element count.
    int N = 1;
    while ((long long)N * N < (long long)out_size) N <<= 1;   // -> 1024
    int T = in_sizes[0] / N;                                   // -> 256

    // Kernel 1: 2N columns * NCHUNK chunks, 256 threads/block.
    int blocks1 = (2 * N + COLS_PER_BLOCK - 1) / COLS_PER_BLOCK;   // 32
    stdp_trace_kernel<<<blocks1, NCHUNK * COLS_PER_BLOCK>>>(pre, post, T, N);

    // Kernel 2: 8 rows per block, N/4 threads.
    stdp_outer_kernel<<<N / ROWS_PER_BLOCK, N / 4>>>(pre, post, out, T, N);
}